// round 12
// baseline (speedup 1.0000x reference)
#include <cuda_runtime.h>
#include <cuda_fp16.h>
#include <math.h>
#include <stdint.h>

#define NSEG 50000
#define NSEG_PAD 50048
#define MROWS 800000
#define KDIM 256   // 2*D
#define ODIM 128

// Scratch (device globals zero-initialized -> padded rows of g_pooled_h are 0)
__device__ int    g_starts[NSEG + 1];
__device__ __half g_pooled_h[(long long)NSEG_PAD * KDIM];   // 25.6 MB
__device__ __half g_W_h[ODIM * KDIM];                       // 64 KB

// ---------------------------------------------------------------------------
// Kernel 1: segment boundary detection (restored R10 known-good) with the
// W fp32->fp16 conversion folded into the first 32 blocks.
// ---------------------------------------------------------------------------
__global__ void boundary_kernel(const void* __restrict__ segraw,
                                const float* __restrict__ W) {
    int t = blockIdx.x * blockDim.x + threadIdx.x;

    if (blockIdx.x < 32) {           // 32 blocks x 256 threads = 8192 float4
        float4 v = ((const float4*)W)[t];
        __half2 h01 = __float22half2_rn(make_float2(v.x, v.y));
        __half2 h23 = __float22half2_rn(make_float2(v.z, v.w));
        uint2 u;
        u.x = *(uint32_t*)&h01;
        u.y = *(uint32_t*)&h23;
        ((uint2*)g_W_h)[t] = u;
    }

    int base = t * 4;
    if (base >= MROWS) return;
    const int* s32 = (const int*)segraw;
    bool is64 = (s32[MROWS - 1] == 0);   // high half of last little-endian int64
    int v[5];
    if (is64) {
        const long long* s = (const long long*)segraw;
        v[0] = (base > 0) ? (int)s[base - 1] : -1;
        longlong2 a = *(const longlong2*)&s[base];
        longlong2 b = *(const longlong2*)&s[base + 2];
        v[1] = (int)a.x; v[2] = (int)a.y; v[3] = (int)b.x; v[4] = (int)b.y;
    } else {
        v[0] = (base > 0) ? s32[base - 1] : -1;
        int4 a = *(const int4*)&s32[base];
        v[1] = a.x; v[2] = a.y; v[3] = a.z; v[4] = a.w;
    }
#pragma unroll
    for (int j = 0; j < 4; ++j)
        if (v[j + 1] != v[j]) g_starts[v[j + 1]] = base + j;
    if (base == 0) g_starts[NSEG] = MROWS;
}

// ---------------------------------------------------------------------------
// Kernel 2: segmented max+mean pooling (byte-identical to R9/R10 known-good).
// ---------------------------------------------------------------------------
__global__ void pool_kernel(const float* __restrict__ lane) {
    int warp = threadIdx.x >> 5;
    int lid  = threadIdx.x & 31;
    int n = blockIdx.x * 4 + warp;
    if (n >= NSEG) return;
    int start = g_starts[n];
    int len   = g_starts[n + 1] - start;

    const float4* p = reinterpret_cast<const float4*>(lane) + (long long)start * 32 + lid;

    float4 m0 = make_float4(-INFINITY, -INFINITY, -INFINITY, -INFINITY);
    float4 m1 = m0;
    float4 s0 = make_float4(0.f, 0.f, 0.f, 0.f);
    float4 s1 = s0;

    int r = 0;
    for (; r + 4 <= len; r += 4) {
        float4 v0 = __ldcs(p);
        float4 v1 = __ldcs(p + 32);
        float4 v2 = __ldcs(p + 64);
        float4 v3 = __ldcs(p + 96);
        p += 128;
        m0.x = fmaxf(m0.x, v0.x); s0.x += v0.x;
        m0.y = fmaxf(m0.y, v0.y); s0.y += v0.y;
        m0.z = fmaxf(m0.z, v0.z); s0.z += v0.z;
        m0.w = fmaxf(m0.w, v0.w); s0.w += v0.w;
        m1.x = fmaxf(m1.x, v1.x); s1.x += v1.x;
        m1.y = fmaxf(m1.y, v1.y); s1.y += v1.y;
        m1.z = fmaxf(m1.z, v1.z); s1.z += v1.z;
        m1.w = fmaxf(m1.w, v1.w); s1.w += v1.w;
        m0.x = fmaxf(m0.x, v2.x); s0.x += v2.x;
        m0.y = fmaxf(m0.y, v2.y); s0.y += v2.y;
        m0.z = fmaxf(m0.z, v2.z); s0.z += v2.z;
        m0.w = fmaxf(m0.w, v2.w); s0.w += v2.w;
        m1.x = fmaxf(m1.x, v3.x); s1.x += v3.x;
        m1.y = fmaxf(m1.y, v3.y); s1.y += v3.y;
        m1.z = fmaxf(m1.z, v3.z); s1.z += v3.z;
        m1.w = fmaxf(m1.w, v3.w); s1.w += v3.w;
    }
    for (; r < len; ++r) {
        float4 v = __ldcs(p);
        p += 32;
        m0.x = fmaxf(m0.x, v.x); s0.x += v.x;
        m0.y = fmaxf(m0.y, v.y); s0.y += v.y;
        m0.z = fmaxf(m0.z, v.z); s0.z += v.z;
        m0.w = fmaxf(m0.w, v.w); s0.w += v.w;
    }

    float4 mx, sm;
    mx.x = fmaxf(m0.x, m1.x); sm.x = s0.x + s1.x;
    mx.y = fmaxf(m0.y, m1.y); sm.y = s0.y + s1.y;
    mx.z = fmaxf(m0.z, m1.z); sm.z = s0.z + s1.z;
    mx.w = fmaxf(m0.w, m1.w); sm.w = s0.w + s1.w;

    float inv = 1.0f / (float)len;
    __half* row = g_pooled_h + (long long)n * KDIM;
    {
        __half2 h01 = __float22half2_rn(make_float2(mx.x, mx.y));
        __half2 h23 = __float22half2_rn(make_float2(mx.z, mx.w));
        uint2 u; u.x = *(uint32_t*)&h01; u.y = *(uint32_t*)&h23;
        ((uint2*)row)[lid] = u;
    }
    {
        __half2 h01 = __float22half2_rn(make_float2(sm.x * inv, sm.y * inv));
        __half2 h23 = __float22half2_rn(make_float2(sm.z * inv, sm.w * inv));
        uint2 u; u.x = *(uint32_t*)&h01; u.y = *(uint32_t*)&h23;
        ((uint2*)row)[32 + lid] = u;
    }
}

// ---------------------------------------------------------------------------
// Kernel 3: out = relu(pooled @ W^T + b), fp16 mma m16n8k16 with fragments
// loaded DIRECTLY from global (no smem staging, no barriers in main loop).
// A rows (16KB/warp) and W (64KB, shared by all warps & CTAs) stay L1-resident.
// CTA tile 64(M) x 128(N); warps 2(M) x 4(N); warp tile 32x32.
// Fragment layout (m16n8k16.row.col), lane = (g, l4):
//   a0 = A[g][2l4,2l4+1]  a1 = A[g+8][...]  a2 = A[g][2l4+8,+9]  a3 = A[g+8][...]
//   b0 = W[n=g][2l4,2l4+1]  b1 = W[n=g][2l4+8,+9]     (same mapping as R9)
// ---------------------------------------------------------------------------
#define BM 64
#define G_THREADS 256

__device__ __forceinline__ void mma_f16(float* d, uint32_t a0, uint32_t a1,
                                        uint32_t a2, uint32_t a3,
                                        uint32_t b0, uint32_t b1) {
    asm volatile(
        "mma.sync.aligned.m16n8k16.row.col.f32.f16.f16.f32 "
        "{%0,%1,%2,%3}, {%4,%5,%6,%7}, {%8,%9}, {%0,%1,%2,%3};"
        : "+f"(d[0]), "+f"(d[1]), "+f"(d[2]), "+f"(d[3])
        : "r"(a0), "r"(a1), "r"(a2), "r"(a3), "r"(b0), "r"(b1));
}

__global__ __launch_bounds__(G_THREADS, 3) void gemm_kernel(const float* __restrict__ bias,
                                                            float* __restrict__ out) {
    __shared__ float sbias[ODIM];

    const int tid  = threadIdx.x;
    const int wid  = tid >> 5;
    const int lane = tid & 31;
    const int g    = lane >> 2;
    const int l4   = lane & 3;
    const int warpM = wid >> 2;     // 0..1
    const int warpN = wid & 3;      // 0..3
    const int bm = blockIdx.x * BM;

    if (tid < ODIM) sbias[tid] = bias[tid];
    __syncthreads();

    // Per-lane row base pointers (k offset added per step), as uint32 loads.
    const uint32_t* A0 = (const uint32_t*)(g_pooled_h +
                         (long long)(bm + warpM * 32 + g) * KDIM) + l4;      // row g
    const uint32_t* A1 = A0 + 4 * KDIM;     // row g+8   (8*KDIM halves / 2)
    const uint32_t* A2 = A0 + 8 * KDIM;     // i=1 row g
    const uint32_t* A3 = A0 + 12 * KDIM;    // i=1 row g+8
    const uint32_t* B0 = (const uint32_t*)(g_W_h + (warpN * 32 + g) * KDIM) + l4;
    const uint32_t* B1 = B0 + 4 * KDIM;     // n-tile 1 (rows +8)
    const uint32_t* B2 = B0 + 8 * KDIM;
    const uint32_t* B3 = B0 + 12 * KDIM;

    float acc[2][4][4];
#pragma unroll
    for (int i = 0; i < 2; ++i)
#pragma unroll
        for (int j = 0; j < 4; ++j)
#pragma unroll
            for (int c = 0; c < 4; ++c) acc[i][j][c] = 0.f;

#pragma unroll 2
    for (int kk = 0; kk < KDIM / 16; ++kk) {
        const int k2 = kk * 8;   // uint32 offset for this k16 step (16 halves)
        uint32_t a[2][4];
        a[0][0] = A0[k2];     a[0][1] = A1[k2];
        a[0][2] = A0[k2 + 4]; a[0][3] = A1[k2 + 4];
        a[1][0] = A2[k2];     a[1][1] = A3[k2];
        a[1][2] = A2[k2 + 4]; a[1][3] = A3[k2 + 4];
        uint32_t b[4][2];
        b[0][0] = B0[k2]; b[0][1] = B0[k2 + 4];
        b[1][0] = B1[k2]; b[1][1] = B1[k2 + 4];
        b[2][0] = B2[k2]; b[2][1] = B2[k2 + 4];
        b[3][0] = B3[k2]; b[3][1] = B3[k2 + 4];
#pragma unroll
        for (int i = 0; i < 2; ++i)
#pragma unroll
            for (int j = 0; j < 4; ++j)
                mma_f16(acc[i][j], a[i][0], a[i][1], a[i][2], a[i][3],
                        b[j][0], b[j][1]);
    }

    // Epilogue: bias + relu, float2 stores (same mapping as R9/R10).
#pragma unroll
    for (int i = 0; i < 2; ++i) {
        int r0 = bm + warpM * 32 + i * 16 + g;
#pragma unroll
        for (int j = 0; j < 4; ++j) {
            int col = warpN * 32 + j * 8 + 2 * l4;
            float bx = sbias[col], by = sbias[col + 1];
            if (r0 < NSEG) {
                float2 o;
                o.x = fmaxf(acc[i][j][0] + bx, 0.f);
                o.y = fmaxf(acc[i][j][1] + by, 0.f);
                *(float2*)&out[(long long)r0 * ODIM + col] = o;
            }
            if (r0 + 8 < NSEG) {
                float2 o;
                o.x = fmaxf(acc[i][j][2] + bx, 0.f);
                o.y = fmaxf(acc[i][j][3] + by, 0.f);
                *(float2*)&out[(long long)(r0 + 8) * ODIM + col] = o;
            }
        }
    }
}

// ---------------------------------------------------------------------------
// Inputs (metadata order): obs_encoding (unused), lane_encoding, same_obs_mask,
// W, b. Output: float32 [NSEG, ODIM].
// ---------------------------------------------------------------------------
extern "C" void kernel_launch(void* const* d_in, const int* in_sizes, int n_in,
                              void* d_out, int out_size) {
    const float* lane = (const float*)d_in[1];
    const void*  seg  = d_in[2];
    const float* W    = (const float*)d_in[3];
    const float* bias = (const float*)d_in[4];
    float* out = (float*)d_out;

    boundary_kernel<<<(MROWS / 4 + 255) / 256, 256>>>(seg, W);
    pool_kernel<<<(NSEG + 3) / 4, 128>>>(lane);
    gemm_kernel<<<NSEG_PAD / BM, G_THREADS>>>(bias, out);
}

// round 14
// speedup vs baseline: 1.2592x; 1.2592x over previous
#include <cuda_runtime.h>
#include <cuda_fp16.h>
#include <math.h>
#include <stdint.h>

#define NSEG 50000
#define NSEG_PAD 50048
#define MROWS 800000
#define KDIM 256   // 2*D
#define ODIM 128

#define POOL_BLOCKS 6250            // 8 segments per block
#define GEMM_BLOCKS 782             // 64 rows per block
#define TOTAL_BLOCKS (POOL_BLOCKS + GEMM_BLOCKS)   // 7032
#define FULL_PERIODS 781            // bids [0, 7029) in 9-block periods

// Scratch (zero-init: padded pooled rows stay 0 forever; g_ready reset per run)
__device__ int    g_starts[NSEG + 1];
__device__ int    g_ready[GEMM_BLOCKS];
__device__ __half g_pooled_h[(long long)NSEG_PAD * KDIM];   // 25.6 MB
__device__ __half g_W_h[ODIM * KDIM];                       // 64 KB

// ---------------------------------------------------------------------------
// Kernel 1: boundary detection + W fp32->fp16 fold-in + g_ready reset.
// ---------------------------------------------------------------------------
__global__ void boundary_kernel(const void* __restrict__ segraw,
                                const float* __restrict__ W) {
    int t = blockIdx.x * blockDim.x + threadIdx.x;

    if (blockIdx.x < 32) {           // 32 blocks x 256 threads = 8192 float4
        float4 v = ((const float4*)W)[t];
        __half2 h01 = __float22half2_rn(make_float2(v.x, v.y));
        __half2 h23 = __float22half2_rn(make_float2(v.z, v.w));
        uint2 u;
        u.x = *(uint32_t*)&h01;
        u.y = *(uint32_t*)&h23;
        ((uint2*)g_W_h)[t] = u;
    }
    if (t < GEMM_BLOCKS) g_ready[t] = 0;   // reset flags every launch/replay

    int base = t * 4;
    if (base >= MROWS) return;
    const int* s32 = (const int*)segraw;
    bool is64 = (s32[MROWS - 1] == 0);   // high half of last little-endian int64
    int v[5];
    if (is64) {
        const long long* s = (const long long*)segraw;
        v[0] = (base > 0) ? (int)s[base - 1] : -1;
        longlong2 a = *(const longlong2*)&s[base];
        longlong2 b = *(const longlong2*)&s[base + 2];
        v[1] = (int)a.x; v[2] = (int)a.y; v[3] = (int)b.x; v[4] = (int)b.y;
    } else {
        v[0] = (base > 0) ? s32[base - 1] : -1;
        int4 a = *(const int4*)&s32[base];
        v[1] = a.x; v[2] = a.y; v[3] = a.z; v[4] = a.w;
    }
#pragma unroll
    for (int j = 0; j < 4; ++j)
        if (v[j + 1] != v[j]) g_starts[v[j + 1]] = base + j;
    if (base == 0) g_starts[NSEG] = MROWS;
}

// ---------------------------------------------------------------------------
// Mega kernel: pool blocks and gemm blocks in ONE grid, interleaved so each
// gemm block (bid%9==8) follows its 8 producer pool blocks in bid order.
// Pool role: 8 warps x 1 segment (R5/R10 known-good streaming loop, fp16 out).
// Gemm role: spin on g_ready, then R10 fp16 mma pipeline with NSTAGE=2.
// ---------------------------------------------------------------------------
#define BM 64
#define BK 32
#define SSTR 40        // smem row stride in halves (80B; ldmatrix conflict-free)
#define NSTAGE 2
#define NSTEPS (KDIM / BK)

__device__ __forceinline__ void cpasync16(uint32_t dst, const void* src) {
    asm volatile("cp.async.cg.shared.global [%0], [%1], 16;" :: "r"(dst), "l"(src));
}
__device__ __forceinline__ void ldmx4(uint32_t& r0, uint32_t& r1, uint32_t& r2,
                                      uint32_t& r3, uint32_t addr) {
    asm volatile("ldmatrix.sync.aligned.m8n8.x4.shared.b16 {%0,%1,%2,%3}, [%4];"
                 : "=r"(r0), "=r"(r1), "=r"(r2), "=r"(r3) : "r"(addr));
}
__device__ __forceinline__ void mma_f16(float* d, uint32_t a0, uint32_t a1,
                                        uint32_t a2, uint32_t a3,
                                        uint32_t b0, uint32_t b1) {
    asm volatile(
        "mma.sync.aligned.m16n8k16.row.col.f32.f16.f16.f32 "
        "{%0,%1,%2,%3}, {%4,%5,%6,%7}, {%8,%9}, {%0,%1,%2,%3};"
        : "+f"(d[0]), "+f"(d[1]), "+f"(d[2]), "+f"(d[3])
        : "r"(a0), "r"(a1), "r"(a2), "r"(a3), "r"(b0), "r"(b1));
}

__global__ __launch_bounds__(256) void mega_kernel(const float* __restrict__ lane,
                                                   const float* __restrict__ bias,
                                                   float* __restrict__ out) {
    __shared__ __align__(16) __half As[NSTAGE][BM][SSTR];
    __shared__ __align__(16) __half Bs[NSTAGE][ODIM][SSTR];
    __shared__ float sbias[ODIM];

    const int bid = blockIdx.x;
    const int tid = threadIdx.x;
    const int wid = tid >> 5;
    const int lid = tid & 31;

    // bid -> role mapping (period 9: 8 pool blocks then 1 gemm block)
    int gblk = -1, pblk = -1;
    if (bid >= FULL_PERIODS * 9) {
        int r = bid - FULL_PERIODS * 9;       // 0..2
        if (r == 2) gblk = FULL_PERIODS;      // 781
        else        pblk = FULL_PERIODS * 8 + r;   // 6248, 6249
    } else if ((bid % 9) == 8) {
        gblk = bid / 9;
    } else {
        pblk = (bid / 9) * 8 + (bid % 9);
    }

    if (pblk >= 0) {
        // ---------------- Pool role: segment n = pblk*8 + wid ----------------
        int n = pblk * 8 + wid;               // always < NSEG (6250*8 == 50000)
        int start = g_starts[n];
        int len   = g_starts[n + 1] - start;

        const float4* p = reinterpret_cast<const float4*>(lane)
                          + (long long)start * 32 + lid;

        float4 m0 = make_float4(-INFINITY, -INFINITY, -INFINITY, -INFINITY);
        float4 m1 = m0;
        float4 s0 = make_float4(0.f, 0.f, 0.f, 0.f);
        float4 s1 = s0;

        int r = 0;
        for (; r + 4 <= len; r += 4) {
            float4 v0 = __ldcs(p);
            float4 v1 = __ldcs(p + 32);
            float4 v2 = __ldcs(p + 64);
            float4 v3 = __ldcs(p + 96);
            p += 128;
            m0.x = fmaxf(m0.x, v0.x); s0.x += v0.x;
            m0.y = fmaxf(m0.y, v0.y); s0.y += v0.y;
            m0.z = fmaxf(m0.z, v0.z); s0.z += v0.z;
            m0.w = fmaxf(m0.w, v0.w); s0.w += v0.w;
            m1.x = fmaxf(m1.x, v1.x); s1.x += v1.x;
            m1.y = fmaxf(m1.y, v1.y); s1.y += v1.y;
            m1.z = fmaxf(m1.z, v1.z); s1.z += v1.z;
            m1.w = fmaxf(m1.w, v1.w); s1.w += v1.w;
            m0.x = fmaxf(m0.x, v2.x); s0.x += v2.x;
            m0.y = fmaxf(m0.y, v2.y); s0.y += v2.y;
            m0.z = fmaxf(m0.z, v2.z); s0.z += v2.z;
            m0.w = fmaxf(m0.w, v2.w); s0.w += v2.w;
            m1.x = fmaxf(m1.x, v3.x); s1.x += v3.x;
            m1.y = fmaxf(m1.y, v3.y); s1.y += v3.y;
            m1.z = fmaxf(m1.z, v3.z); s1.z += v3.z;
            m1.w = fmaxf(m1.w, v3.w); s1.w += v3.w;
        }
        for (; r < len; ++r) {
            float4 v = __ldcs(p);
            p += 32;
            m0.x = fmaxf(m0.x, v.x); s0.x += v.x;
            m0.y = fmaxf(m0.y, v.y); s0.y += v.y;
            m0.z = fmaxf(m0.z, v.z); s0.z += v.z;
            m0.w = fmaxf(m0.w, v.w); s0.w += v.w;
        }

        float4 mx, sm;
        mx.x = fmaxf(m0.x, m1.x); sm.x = s0.x + s1.x;
        mx.y = fmaxf(m0.y, m1.y); sm.y = s0.y + s1.y;
        mx.z = fmaxf(m0.z, m1.z); sm.z = s0.z + s1.z;
        mx.w = fmaxf(m0.w, m1.w); sm.w = s0.w + s1.w;

        float inv = 1.0f / (float)len;
        __half* row = g_pooled_h + (long long)n * KDIM;
        {
            __half2 h01 = __float22half2_rn(make_float2(mx.x, mx.y));
            __half2 h23 = __float22half2_rn(make_float2(mx.z, mx.w));
            uint2 u; u.x = *(uint32_t*)&h01; u.y = *(uint32_t*)&h23;
            ((uint2*)row)[lid] = u;
        }
        {
            __half2 h01 = __float22half2_rn(make_float2(sm.x * inv, sm.y * inv));
            __half2 h23 = __float22half2_rn(make_float2(sm.z * inv, sm.w * inv));
            uint2 u; u.x = *(uint32_t*)&h01; u.y = *(uint32_t*)&h23;
            ((uint2*)row)[32 + lid] = u;
        }

        __syncthreads();                       // all 8 segments of this block done
        if (tid == 0) {
            __threadfence();                   // release: pooled rows visible at L2
            atomicAdd(&g_ready[pblk >> 3], 1);
        }
        return;
    }

    // ---------------- Gemm role: rows [gblk*64, gblk*64+64) ----------------
    const int bm = gblk * BM;

    if (tid < ODIM) sbias[tid] = bias[tid];

    if (tid == 0) {
        int target = POOL_BLOCKS - 8 * gblk;   // 8 normally; 2 for the last block
        if (target > 8) target = 8;
        while (((volatile int*)g_ready)[gblk] < target) __nanosleep(128);
        __threadfence();                       // acquire before reading pooled data
    }
    __syncthreads();

    const int lane32 = tid & 31;
    const int g  = lane32 >> 2;
    const int l4 = lane32 & 3;
    const int warpM = wid >> 2;     // 0..1
    const int warpN = wid & 3;      // 0..3

    const int arow = tid >> 2, ac8 = tid & 3;
    uint32_t as_base = (uint32_t)__cvta_generic_to_shared(&As[0][0][0]);
    uint32_t bs_base = (uint32_t)__cvta_generic_to_shared(&Bs[0][0][0]);

    const int jj = lane32 >> 3;
    const int rowoff = ((jj & 1) << 3) + (lane32 & 7);
    const int koff = (jj >> 1) << 3;
    uint32_t aoff[2], boff[2];
#pragma unroll
    for (int i = 0; i < 2; ++i)
        aoff[i] = ((warpM * 32 + i * 16 + rowoff) * SSTR + koff) * 2;
#pragma unroll
    for (int p = 0; p < 2; ++p)
        boff[p] = ((warpN * 32 + p * 16 + rowoff) * SSTR + koff) * 2;

    float acc[2][4][4];
#pragma unroll
    for (int i = 0; i < 2; ++i)
#pragma unroll
        for (int j = 0; j < 4; ++j)
#pragma unroll
            for (int c = 0; c < 4; ++c) acc[i][j][c] = 0.f;

    auto issue_stage = [&](int step) {
        int s = step % NSTAGE;
        int kt = step * BK;
        cpasync16(as_base + (((s * BM + arow) * SSTR) + ac8 * 8) * 2,
                  &g_pooled_h[(long long)(bm + arow) * KDIM + kt + ac8 * 8]);
#pragma unroll
        for (int i = 0; i < 2; ++i) {
            int idx = tid + i * 256;
            int row = idx >> 2, c8 = idx & 3;
            cpasync16(bs_base + (((s * ODIM + row) * SSTR) + c8 * 8) * 2,
                      &g_W_h[row * KDIM + kt + c8 * 8]);
        }
        asm volatile("cp.async.commit_group;" ::: "memory");
    };

    issue_stage(0);
    issue_stage(1);

#pragma unroll 1
    for (int step = 0; step < NSTEPS; ++step) {
        if (step < NSTEPS - 1) {
            asm volatile("cp.async.wait_group 1;" ::: "memory");
        } else {
            asm volatile("cp.async.wait_group 0;" ::: "memory");
        }
        __syncthreads();

        const int s = step % NSTAGE;
        uint32_t abase = as_base + s * BM * SSTR * 2;
        uint32_t bbase = bs_base + s * ODIM * SSTR * 2;
#pragma unroll
        for (int kk = 0; kk < BK / 16; ++kk) {
            const uint32_t kb = kk * 32;
            uint32_t a[2][4];
#pragma unroll
            for (int i = 0; i < 2; ++i)
                ldmx4(a[i][0], a[i][1], a[i][2], a[i][3], abase + aoff[i] + kb);
            uint32_t b[2][4];
#pragma unroll
            for (int p = 0; p < 2; ++p)
                ldmx4(b[p][0], b[p][1], b[p][2], b[p][3], bbase + boff[p] + kb);
#pragma unroll
            for (int i = 0; i < 2; ++i)
#pragma unroll
                for (int j = 0; j < 4; ++j) {
                    int p = j >> 1, o = j & 1;
                    mma_f16(acc[i][j], a[i][0], a[i][1], a[i][2], a[i][3],
                            b[p][o], b[p][o + 2]);
                }
        }
        __syncthreads();
        if (step + 2 < NSTEPS) issue_stage(step + 2);
    }

    // Epilogue: bias + relu, float2 stores.
#pragma unroll
    for (int i = 0; i < 2; ++i) {
        int r0 = bm + warpM * 32 + i * 16 + g;
#pragma unroll
        for (int j = 0; j < 4; ++j) {
            int col = warpN * 32 + j * 8 + 2 * l4;
            float bx = sbias[col], by = sbias[col + 1];
            if (r0 < NSEG) {
                float2 o;
                o.x = fmaxf(acc[i][j][0] + bx, 0.f);
                o.y = fmaxf(acc[i][j][1] + by, 0.f);
                *(float2*)&out[(long long)r0 * ODIM + col] = o;
            }
            if (r0 + 8 < NSEG) {
                float2 o;
                o.x = fmaxf(acc[i][j][2] + bx, 0.f);
                o.y = fmaxf(acc[i][j][3] + by, 0.f);
                *(float2*)&out[(long long)(r0 + 8) * ODIM + col] = o;
            }
        }
    }
}

// ---------------------------------------------------------------------------
// Inputs (metadata order): obs_encoding (unused), lane_encoding, same_obs_mask,
// W, b. Output: float32 [NSEG, ODIM].
// ---------------------------------------------------------------------------
extern "C" void kernel_launch(void* const* d_in, const int* in_sizes, int n_in,
                              void* d_out, int out_size) {
    const float* lane = (const float*)d_in[1];
    const void*  seg  = d_in[2];
    const float* W    = (const float*)d_in[3];
    const float* bias = (const float*)d_in[4];
    float* out = (float*)d_out;

    boundary_kernel<<<(MROWS / 4 + 255) / 256, 256>>>(seg, W);
    mega_kernel<<<TOTAL_BLOCKS, 256>>>(lane, bias, out);
}

// round 15
// speedup vs baseline: 1.4010x; 1.1126x over previous
#include <cuda_runtime.h>
#include <cuda_fp16.h>
#include <math.h>
#include <stdint.h>

#define NSEG 50000
#define NSEG_PAD 50048
#define MROWS 800000
#define KDIM 256   // 2*D
#define ODIM 128

// Scratch (device globals zero-initialized -> padded rows of g_pooled_h are 0)
__device__ int    g_starts[NSEG + 1];
__device__ __half g_pooled_h[(long long)NSEG_PAD * KDIM];   // 25.6 MB
__device__ __half g_W_h[ODIM * KDIM];                       // 64 KB

// ---------------------------------------------------------------------------
// Kernel 1: segment boundary detection + W fp32->fp16 fold-in (R12-verified).
// ---------------------------------------------------------------------------
__global__ void boundary_kernel(const void* __restrict__ segraw,
                                const float* __restrict__ W) {
    int t = blockIdx.x * blockDim.x + threadIdx.x;

    if (blockIdx.x < 32) {           // 32 blocks x 256 threads = 8192 float4
        float4 v = ((const float4*)W)[t];
        __half2 h01 = __float22half2_rn(make_float2(v.x, v.y));
        __half2 h23 = __float22half2_rn(make_float2(v.z, v.w));
        uint2 u;
        u.x = *(uint32_t*)&h01;
        u.y = *(uint32_t*)&h23;
        ((uint2*)g_W_h)[t] = u;
    }

    int base = t * 4;
    if (base >= MROWS) return;
    const int* s32 = (const int*)segraw;
    bool is64 = (s32[MROWS - 1] == 0);   // high half of last little-endian int64
    int v[5];
    if (is64) {
        const long long* s = (const long long*)segraw;
        v[0] = (base > 0) ? (int)s[base - 1] : -1;
        longlong2 a = *(const longlong2*)&s[base];
        longlong2 b = *(const longlong2*)&s[base + 2];
        v[1] = (int)a.x; v[2] = (int)a.y; v[3] = (int)b.x; v[4] = (int)b.y;
    } else {
        v[0] = (base > 0) ? s32[base - 1] : -1;
        int4 a = *(const int4*)&s32[base];
        v[1] = a.x; v[2] = a.y; v[3] = a.z; v[4] = a.w;
    }
#pragma unroll
    for (int j = 0; j < 4; ++j)
        if (v[j + 1] != v[j]) g_starts[v[j + 1]] = base + j;
    if (base == 0) g_starts[NSEG] = MROWS;
}

// ---------------------------------------------------------------------------
// Kernel 2: segmented max+mean pooling (byte-identical to R9/R10 known-good).
// ---------------------------------------------------------------------------
__global__ void pool_kernel(const float* __restrict__ lane) {
    int warp = threadIdx.x >> 5;
    int lid  = threadIdx.x & 31;
    int n = blockIdx.x * 4 + warp;
    if (n >= NSEG) return;
    int start = g_starts[n];
    int len   = g_starts[n + 1] - start;

    const float4* p = reinterpret_cast<const float4*>(lane) + (long long)start * 32 + lid;

    float4 m0 = make_float4(-INFINITY, -INFINITY, -INFINITY, -INFINITY);
    float4 m1 = m0;
    float4 s0 = make_float4(0.f, 0.f, 0.f, 0.f);
    float4 s1 = s0;

    int r = 0;
    for (; r + 4 <= len; r += 4) {
        float4 v0 = __ldcs(p);
        float4 v1 = __ldcs(p + 32);
        float4 v2 = __ldcs(p + 64);
        float4 v3 = __ldcs(p + 96);
        p += 128;
        m0.x = fmaxf(m0.x, v0.x); s0.x += v0.x;
        m0.y = fmaxf(m0.y, v0.y); s0.y += v0.y;
        m0.z = fmaxf(m0.z, v0.z); s0.z += v0.z;
        m0.w = fmaxf(m0.w, v0.w); s0.w += v0.w;
        m1.x = fmaxf(m1.x, v1.x); s1.x += v1.x;
        m1.y = fmaxf(m1.y, v1.y); s1.y += v1.y;
        m1.z = fmaxf(m1.z, v1.z); s1.z += v1.z;
        m1.w = fmaxf(m1.w, v1.w); s1.w += v1.w;
        m0.x = fmaxf(m0.x, v2.x); s0.x += v2.x;
        m0.y = fmaxf(m0.y, v2.y); s0.y += v2.y;
        m0.z = fmaxf(m0.z, v2.z); s0.z += v2.z;
        m0.w = fmaxf(m0.w, v2.w); s0.w += v2.w;
        m1.x = fmaxf(m1.x, v3.x); s1.x += v3.x;
        m1.y = fmaxf(m1.y, v3.y); s1.y += v3.y;
        m1.z = fmaxf(m1.z, v3.z); s1.z += v3.z;
        m1.w = fmaxf(m1.w, v3.w); s1.w += v3.w;
    }
    for (; r < len; ++r) {
        float4 v = __ldcs(p);
        p += 32;
        m0.x = fmaxf(m0.x, v.x); s0.x += v.x;
        m0.y = fmaxf(m0.y, v.y); s0.y += v.y;
        m0.z = fmaxf(m0.z, v.z); s0.z += v.z;
        m0.w = fmaxf(m0.w, v.w); s0.w += v.w;
    }

    float4 mx, sm;
    mx.x = fmaxf(m0.x, m1.x); sm.x = s0.x + s1.x;
    mx.y = fmaxf(m0.y, m1.y); sm.y = s0.y + s1.y;
    mx.z = fmaxf(m0.z, m1.z); sm.z = s0.z + s1.z;
    mx.w = fmaxf(m0.w, m1.w); sm.w = s0.w + s1.w;

    float inv = 1.0f / (float)len;
    __half* row = g_pooled_h + (long long)n * KDIM;
    {
        __half2 h01 = __float22half2_rn(make_float2(mx.x, mx.y));
        __half2 h23 = __float22half2_rn(make_float2(mx.z, mx.w));
        uint2 u; u.x = *(uint32_t*)&h01; u.y = *(uint32_t*)&h23;
        ((uint2*)row)[lid] = u;
    }
    {
        __half2 h01 = __float22half2_rn(make_float2(sm.x * inv, sm.y * inv));
        __half2 h23 = __float22half2_rn(make_float2(sm.z * inv, sm.w * inv));
        uint2 u; u.x = *(uint32_t*)&h01; u.y = *(uint32_t*)&h23;
        ((uint2*)row)[32 + lid] = u;
    }
}

// ---------------------------------------------------------------------------
// Kernel 3: out = relu(pooled @ W^T + b), fp16 mma m16n8k16 + ldmatrix,
// 2-stage cp.async pipeline. NSTAGE=2 -> 30.5KB smem -> 7 CTAs/SM, so all
// 782 CTAs are co-resident: the gemm is ONE wave (vs two at NSTAGE=3).
// CTA tile 64(M) x 128(N), BK=32 halves, 8 steps. Warps 2(M) x 4(N).
// ---------------------------------------------------------------------------
#define BM 64
#define BK 32          // halves per stage
#define SSTR 40        // smem row stride in halves (80B; ldmatrix conflict-free)
#define NSTAGE 2
#define NSTEPS (KDIM / BK)
#define G_THREADS 256

__device__ __forceinline__ void cpasync16(uint32_t dst, const void* src) {
    asm volatile("cp.async.cg.shared.global [%0], [%1], 16;" :: "r"(dst), "l"(src));
}
__device__ __forceinline__ void ldmx4(uint32_t& r0, uint32_t& r1, uint32_t& r2,
                                      uint32_t& r3, uint32_t addr) {
    asm volatile("ldmatrix.sync.aligned.m8n8.x4.shared.b16 {%0,%1,%2,%3}, [%4];"
                 : "=r"(r0), "=r"(r1), "=r"(r2), "=r"(r3) : "r"(addr));
}
__device__ __forceinline__ void mma_f16(float* d, uint32_t a0, uint32_t a1,
                                        uint32_t a2, uint32_t a3,
                                        uint32_t b0, uint32_t b1) {
    asm volatile(
        "mma.sync.aligned.m16n8k16.row.col.f32.f16.f16.f32 "
        "{%0,%1,%2,%3}, {%4,%5,%6,%7}, {%8,%9}, {%0,%1,%2,%3};"
        : "+f"(d[0]), "+f"(d[1]), "+f"(d[2]), "+f"(d[3])
        : "r"(a0), "r"(a1), "r"(a2), "r"(a3), "r"(b0), "r"(b1));
}

__global__ __launch_bounds__(G_THREADS) void gemm_kernel(const float* __restrict__ bias,
                                                         float* __restrict__ out) {
    __shared__ __align__(16) __half As[NSTAGE][BM][SSTR];
    __shared__ __align__(16) __half Bs[NSTAGE][ODIM][SSTR];
    __shared__ float sbias[ODIM];

    const int tid  = threadIdx.x;
    const int wid  = tid >> 5;
    const int lane = tid & 31;
    const int g    = lane >> 2;
    const int l4   = lane & 3;
    const int warpM = wid >> 2;     // 0..1
    const int warpN = wid & 3;      // 0..3
    const int bm = blockIdx.x * BM;

    if (tid < ODIM) sbias[tid] = bias[tid];

    const int arow = tid >> 2, ac8 = tid & 3;
    uint32_t as_base = (uint32_t)__cvta_generic_to_shared(&As[0][0][0]);
    uint32_t bs_base = (uint32_t)__cvta_generic_to_shared(&Bs[0][0][0]);

    // ldmatrix per-lane addressing
    const int jj = lane >> 3;
    const int rowoff = ((jj & 1) << 3) + (lane & 7);
    const int koff = (jj >> 1) << 3;
    uint32_t aoff[2], boff[2];
#pragma unroll
    for (int i = 0; i < 2; ++i)
        aoff[i] = ((warpM * 32 + i * 16 + rowoff) * SSTR + koff) * 2;
#pragma unroll
    for (int p = 0; p < 2; ++p)
        boff[p] = ((warpN * 32 + p * 16 + rowoff) * SSTR + koff) * 2;

    float acc[2][4][4];
#pragma unroll
    for (int i = 0; i < 2; ++i)
#pragma unroll
        for (int j = 0; j < 4; ++j)
#pragma unroll
            for (int c = 0; c < 4; ++c) acc[i][j][c] = 0.f;

    auto issue_stage = [&](int step) {
        int s = step % NSTAGE;
        int kt = step * BK;
        cpasync16(as_base + (((s * BM + arow) * SSTR) + ac8 * 8) * 2,
                  &g_pooled_h[(long long)(bm + arow) * KDIM + kt + ac8 * 8]);
#pragma unroll
        for (int i = 0; i < 2; ++i) {
            int idx = tid + i * 256;
            int row = idx >> 2, c8 = idx & 3;
            cpasync16(bs_base + (((s * ODIM + row) * SSTR) + c8 * 8) * 2,
                      &g_W_h[row * KDIM + kt + c8 * 8]);
        }
        asm volatile("cp.async.commit_group;" ::: "memory");
    };

    issue_stage(0);
    issue_stage(1);

#pragma unroll 1
    for (int step = 0; step < NSTEPS; ++step) {
        if (step < NSTEPS - 1) {
            asm volatile("cp.async.wait_group 1;" ::: "memory");
        } else {
            asm volatile("cp.async.wait_group 0;" ::: "memory");
        }
        __syncthreads();

        const int s = step % NSTAGE;
        uint32_t abase = as_base + s * BM * SSTR * 2;
        uint32_t bbase = bs_base + s * ODIM * SSTR * 2;
#pragma unroll
        for (int kk = 0; kk < BK / 16; ++kk) {
            const uint32_t kb = kk * 32;   // 16 halves = 32 bytes
            uint32_t a[2][4];
#pragma unroll
            for (int i = 0; i < 2; ++i)
                ldmx4(a[i][0], a[i][1], a[i][2], a[i][3], abase + aoff[i] + kb);
            uint32_t b[2][4];
#pragma unroll
            for (int p = 0; p < 2; ++p)
                ldmx4(b[p][0], b[p][1], b[p][2], b[p][3], bbase + boff[p] + kb);
#pragma unroll
            for (int i = 0; i < 2; ++i)
#pragma unroll
                for (int j = 0; j < 4; ++j) {
                    int p = j >> 1, o = j & 1;
                    mma_f16(acc[i][j], a[i][0], a[i][1], a[i][2], a[i][3],
                            b[p][o], b[p][o + 2]);
                }
        }
        __syncthreads();   // all warps done reading stage s before it is reused
        if (step + 2 < NSTEPS) issue_stage(step + 2);
    }

    // Epilogue: bias + relu, float2 stores.
#pragma unroll
    for (int i = 0; i < 2; ++i) {
        int r0 = bm + warpM * 32 + i * 16 + g;
#pragma unroll
        for (int j = 0; j < 4; ++j) {
            int col = warpN * 32 + j * 8 + 2 * l4;
            float bx = sbias[col], by = sbias[col + 1];
            if (r0 < NSEG) {
                float2 o;
                o.x = fmaxf(acc[i][j][0] + bx, 0.f);
                o.y = fmaxf(acc[i][j][1] + by, 0.f);
                *(float2*)&out[(long long)r0 * ODIM + col] = o;
            }
            if (r0 + 8 < NSEG) {
                float2 o;
                o.x = fmaxf(acc[i][j][2] + bx, 0.f);
                o.y = fmaxf(acc[i][j][3] + by, 0.f);
                *(float2*)&out[(long long)(r0 + 8) * ODIM + col] = o;
            }
        }
    }
}

// ---------------------------------------------------------------------------
// Inputs (metadata order): obs_encoding (unused), lane_encoding, same_obs_mask,
// W, b. Output: float32 [NSEG, ODIM].
// ---------------------------------------------------------------------------
extern "C" void kernel_launch(void* const* d_in, const int* in_sizes, int n_in,
                              void* d_out, int out_size) {
    const float* lane = (const float*)d_in[1];
    const void*  seg  = d_in[2];
    const float* W    = (const float*)d_in[3];
    const float* bias = (const float*)d_in[4];
    float* out = (float*)d_out;

    boundary_kernel<<<(MROWS / 4 + 255) / 256, 256>>>(seg, W);
    pool_kernel<<<(NSEG + 3) / 4, 128>>>(lane);
    gemm_kernel<<<NSEG_PAD / BM, G_THREADS>>>(bias, out);
}